// round 6
// baseline (speedup 1.0000x reference)
#include <cuda_runtime.h>
#include <cstdint>

#define THREADS   128
#define FDIM      64
#define EDIM      32
#define ROWBYTES  80                  // bf16 per row: 32 data (64 B) + 16 B pad
#define BUFBYTES  (FDIM * ROWBYTES)   // 5120 B per [64][40] bf16 buffer
#define NBUF      12                  // 0..9 = head*2+{h,l} of y; 10 = xh; 11 = xl
#define SMEM_BYTES (NBUF * BUFBYTES)  // 61440

static __device__ __forceinline__ uint32_t pack_bf16x2(float hi, float lo) {
    uint32_t r;
    asm("cvt.rn.bf16x2.f32 %0, %1, %2;" : "=r"(r) : "f"(hi), "f"(lo));
    return r;
}
static __device__ __forceinline__ void ldsm4(uint32_t* r, uint32_t addr) {
    asm volatile("ldmatrix.sync.aligned.m8n8.x4.shared.b16 {%0,%1,%2,%3}, [%4];"
                 : "=r"(r[0]), "=r"(r[1]), "=r"(r[2]), "=r"(r[3]) : "r"(addr));
}
static __device__ __forceinline__ void mma16816(float* d, const uint32_t* a,
                                                uint32_t b0, uint32_t b1) {
    asm volatile("mma.sync.aligned.m16n8k16.row.col.f32.bf16.bf16.f32 "
                 "{%0,%1,%2,%3}, {%4,%5,%6,%7}, {%8,%9}, {%0,%1,%2,%3};"
                 : "+f"(d[0]), "+f"(d[1]), "+f"(d[2]), "+f"(d[3])
                 : "r"(a[0]), "r"(a[1]), "r"(a[2]), "r"(a[3]), "r"(b0), "r"(b1));
}

__global__ void __launch_bounds__(THREADS, 3)
afm_kernel(const float* __restrict__ x,
           const float* __restrict__ attn_w,
           const float* __restrict__ attn_b,
           const float* __restrict__ attn_h,
           const float* __restrict__ pool_w,
           const float* __restrict__ pool_b,
           float* __restrict__ out)
{
    extern __shared__ __align__(16) char sm[];
    __shared__ float w5[EDIM][8];     // [e][0..3]=attn_w, [e][4]=pool_w
    __shared__ float rmax[4], rse[4], rsq[4];
    __shared__ float bmaxs;

    const int t = threadIdx.x;
    const int b = blockIdx.x;
    const float* xb = x + (size_t)b * (FDIM * EDIM);

    // ================= prologue: split x, build 5 y-tables (bf16 hi/lo) ======
    const int f = t & 63;
    const int h = t >> 6;             // e-half: 0 -> e 0..15, 1 -> e 16..31
    const float* src = xb + f * EDIM + h * 16;
    float4 v4[4];
    #pragma unroll
    for (int q = 0; q < 4; q++) v4[q] = reinterpret_cast<const float4*>(src)[q];

    if (t < EDIM) {
        float4 wv = reinterpret_cast<const float4*>(attn_w)[t];
        w5[t][0] = wv.x; w5[t][1] = wv.y; w5[t][2] = wv.z; w5[t][3] = wv.w;
        w5[t][4] = pool_w[t];
    }
    __syncthreads();

    float v[16];
    #pragma unroll
    for (int q = 0; q < 4; q++) {
        v[q * 4 + 0] = v4[q].x; v[q * 4 + 1] = v4[q].y;
        v[q * 4 + 2] = v4[q].z; v[q * 4 + 3] = v4[q].w;
    }

    #pragma unroll
    for (int c = 0; c < 2; c++) {          // chunk of 8 e (4 bf16x2)
        uint32_t xh4[4], xl4[4], yh4[5][4], yl4[5][4];
        #pragma unroll
        for (int p = 0; p < 4; p++) {
            int ei = c * 8 + p * 2;
            int e  = h * 16 + ei;
            float a0 = v[ei], a1 = v[ei + 1];
            uint32_t u0 = __float_as_uint(a0), u1 = __float_as_uint(a1);
            xh4[p] = __byte_perm(u0, u1, 0x7632);            // {hi16(a1),hi16(a0)}
            float t0 = a0 - __uint_as_float(u0 & 0xFFFF0000u);
            float t1 = a1 - __uint_as_float(u1 & 0xFFFF0000u);
            xl4[p] = pack_bf16x2(t1, t0);
            float4 wr0 = *reinterpret_cast<const float4*>(&w5[e][0]);
            float4 wr1 = *reinterpret_cast<const float4*>(&w5[e + 1][0]);
            float wa0[5] = { wr0.x, wr0.y, wr0.z, wr0.w, w5[e][4] };
            float wa1[5] = { wr1.x, wr1.y, wr1.z, wr1.w, w5[e + 1][4] };
            #pragma unroll
            for (int a = 0; a < 5; a++) {
                float y0 = a0 * wa0[a], y1 = a1 * wa1[a];
                uint32_t q0 = __float_as_uint(y0), q1 = __float_as_uint(y1);
                yh4[a][p] = __byte_perm(q0, q1, 0x7632);
                float g0 = y0 - __uint_as_float(q0 & 0xFFFF0000u);
                float g1 = y1 - __uint_as_float(q1 & 0xFFFF0000u);
                yl4[a][p] = pack_bf16x2(g1, g0);
            }
        }
        int off = f * ROWBYTES + h * 32 + c * 16;
        *reinterpret_cast<uint4*>(sm + 10 * BUFBYTES + off) = *reinterpret_cast<uint4*>(xh4);
        *reinterpret_cast<uint4*>(sm + 11 * BUFBYTES + off) = *reinterpret_cast<uint4*>(xl4);
        #pragma unroll
        for (int a = 0; a < 5; a++) {
            *reinterpret_cast<uint4*>(sm + (2 * a + 0) * BUFBYTES + off) = *reinterpret_cast<uint4*>(yh4[a]);
            *reinterpret_cast<uint4*>(sm + (2 * a + 1) * BUFBYTES + off) = *reinterpret_cast<uint4*>(yl4[a]);
        }
    }
    __syncthreads();

    // ====== mainloop: A = x (i side, amortized), B = y_a (j side, per head) ==
    const int lane = t & 31;
    const int w    = t >> 5;
    const int lg = lane >> 3, lr = lane & 7;
    const uint32_t a_off = (uint32_t)(((lg & 1) * 8 + lr) * ROWBYTES + (lg >> 1) * 16);
    const uint32_t b_off = (uint32_t)(lr * ROWBYTES + lg * 16);

    uint32_t smb = (uint32_t)__cvta_generic_to_shared(sm);
    const uint32_t xh_base = smb + 10 * BUFBYTES;
    const uint32_t xl_base = smb + 11 * BUFBYTES;

    const float ba[4] = { attn_b[0], attn_b[1], attn_b[2], attn_b[3] };
    const float ha[4] = { attn_h[0], attn_h[1], attn_h[2], attn_h[3] };

    // tiles grouped by ti so A-frags reload at most once per warp
    const int TI4[4][5] = {{0,0,0,0,0},{0,0,0,1,1},{1,1,1,1,2},{2,2,2,3,3}};
    const int TJ4[4][5] = {{0,1,2,3,4},{5,6,7,2,3},{4,5,6,7,4},{5,6,7,6,7}};

    float sc[5][4], qc[5][4];
    int ti_r[5], tj_r[5];

    uint32_t ah0[4], ah1[4], al0[4], al1[4];
    int prev_ti = -1;

    #pragma unroll
    for (int k = 0; k < 5; k++) {
        const int ti = TI4[w][k], tj = TJ4[w][k];
        ti_r[k] = ti; tj_r[k] = tj;

        if (ti != prev_ti) {
            uint32_t arh = xh_base + (uint32_t)(ti * 16 * ROWBYTES) + a_off;
            uint32_t arl = xl_base + (uint32_t)(ti * 16 * ROWBYTES) + a_off;
            ldsm4(ah0, arh);
            ldsm4(ah1, arh + 32);   // e cols 16..31
            ldsm4(al0, arl);
            ldsm4(al1, arl + 32);
            prev_ti = ti;
        }

        const uint32_t brow = smb + (uint32_t)(tj * 8 * ROWBYTES) + b_off;

        float tsc[4] = {0.f, 0.f, 0.f, 0.f};
        #pragma unroll
        for (int a = 0; a < 5; a++) {
            uint32_t bh[4], bl[4];
            ldsm4(bh, brow + (uint32_t)((2 * a + 0) * BUFBYTES));
            ldsm4(bl, brow + (uint32_t)((2 * a + 1) * BUFBYTES));

            float d[4] = {0.f, 0.f, 0.f, 0.f};
            mma16816(d, ah0, bh[0], bh[1]);   // xh·yh k0
            mma16816(d, ah1, bh[2], bh[3]);   // xh·yh k1
            mma16816(d, ah0, bl[0], bl[1]);   // xh·yl k0
            mma16816(d, ah1, bl[2], bl[3]);   // xh·yl k1
            mma16816(d, al0, bh[0], bh[1]);   // xl·yh k0
            mma16816(d, al1, bh[2], bh[3]);   // xl·yh k1

            if (a < 4) {
                #pragma unroll
                for (int cc = 0; cc < 4; cc++)
                    tsc[cc] += fmaxf(d[cc] + ba[a], 0.f) * ha[a];
            } else {
                #pragma unroll
                for (int cc = 0; cc < 4; cc++) qc[k][cc] = d[cc];
            }
        }
        #pragma unroll
        for (int cc = 0; cc < 4; cc++) sc[k][cc] = tsc[cc];
    }

    // ================= softmax over live cells (i<j) + weighted pool ========
    float lmax = -1e30f;
    #pragma unroll
    for (int k = 0; k < 5; k++)
        #pragma unroll
        for (int cc = 0; cc < 4; cc++) {
            int i = ti_r[k] * 16 + (lane >> 2) + ((cc >= 2) ? 8 : 0);
            int j = tj_r[k] * 8 + 2 * (lane & 3) + (cc & 1);
            if (i < j) lmax = fmaxf(lmax, sc[k][cc]);
        }
    #pragma unroll
    for (int o = 16; o; o >>= 1)
        lmax = fmaxf(lmax, __shfl_xor_sync(0xffffffffu, lmax, o));
    if (lane == 0) rmax[w] = lmax;
    __syncthreads();
    if (t == 0)
        bmaxs = fmaxf(fmaxf(rmax[0], rmax[1]), fmaxf(rmax[2], rmax[3]));
    __syncthreads();
    const float m = bmaxs;

    float se = 0.f, sq = 0.f;
    #pragma unroll
    for (int k = 0; k < 5; k++)
        #pragma unroll
        for (int cc = 0; cc < 4; cc++) {
            int i = ti_r[k] * 16 + (lane >> 2) + ((cc >= 2) ? 8 : 0);
            int j = tj_r[k] * 8 + 2 * (lane & 3) + (cc & 1);
            if (i < j) {
                float ex = __expf(sc[k][cc] - m);
                se += ex;
                sq += ex * qc[k][cc];
            }
        }
    #pragma unroll
    for (int o = 16; o; o >>= 1) {
        se += __shfl_xor_sync(0xffffffffu, se, o);
        sq += __shfl_xor_sync(0xffffffffu, sq, o);
    }
    if (lane == 0) { rse[w] = se; rsq[w] = sq; }
    __syncthreads();
    if (t == 0) {
        float S = rse[0] + rse[1] + rse[2] + rse[3];
        float Q = rsq[0] + rsq[1] + rsq[2] + rsq[3];
        out[b] = Q / S + pool_b[0];
    }
}

extern "C" void kernel_launch(void* const* d_in, const int* in_sizes, int n_in,
                              void* d_out, int out_size)
{
    const float* x      = (const float*)d_in[0];
    const float* attn_w = (const float*)d_in[1];
    const float* attn_b = (const float*)d_in[2];
    const float* attn_h = (const float*)d_in[3];
    const float* pool_w = (const float*)d_in[4];
    const float* pool_b = (const float*)d_in[5];
    float* out = (float*)d_out;

    cudaFuncSetAttribute(afm_kernel, cudaFuncAttributeMaxDynamicSharedMemorySize, SMEM_BYTES);

    int B = in_sizes[0] / (FDIM * EDIM);
    afm_kernel<<<B, THREADS, SMEM_BYTES>>>(x, attn_w, attn_b, attn_h, pool_w, pool_b, out);
}

// round 8
// speedup vs baseline: 1.0570x; 1.0570x over previous
#include <cuda_runtime.h>
#include <cstdint>

#define THREADS   128
#define FDIM      64
#define EDIM      32
#define ROWBYTES  64                  // 32 bf16, XOR-swizzled 16B chunks (no pad)
#define BUFBYTES  (FDIM * ROWBYTES)   // 4096 B per [64][32] bf16 buffer
#define NBUF      12                  // 0..9 = head*2+{h,l} of y; 10 = xh; 11 = xl
#define SMEM_BYTES (NBUF * BUFBYTES)  // 49152

static __device__ __forceinline__ uint32_t pack_bf16x2(float hi, float lo) {
    uint32_t r;
    asm("cvt.rn.bf16x2.f32 %0, %1, %2;" : "=r"(r) : "f"(hi), "f"(lo));
    return r;
}
static __device__ __forceinline__ void ldsm4(uint32_t* r, uint32_t addr) {
    asm volatile("ldmatrix.sync.aligned.m8n8.x4.shared.b16 {%0,%1,%2,%3}, [%4];"
                 : "=r"(r[0]), "=r"(r[1]), "=r"(r[2]), "=r"(r[3]) : "r"(addr));
}
static __device__ __forceinline__ void mma16816(float* d, const uint32_t* a,
                                                uint32_t b0, uint32_t b1) {
    asm volatile("mma.sync.aligned.m16n8k16.row.col.f32.bf16.bf16.f32 "
                 "{%0,%1,%2,%3}, {%4,%5,%6,%7}, {%8,%9}, {%0,%1,%2,%3};"
                 : "+f"(d[0]), "+f"(d[1]), "+f"(d[2]), "+f"(d[3])
                 : "r"(a[0]), "r"(a[1]), "r"(a[2]), "r"(a[3]), "r"(b0), "r"(b1));
}

__global__ void __launch_bounds__(THREADS, 4)
afm_kernel(const float* __restrict__ x,
           const float* __restrict__ attn_w,
           const float* __restrict__ attn_b,
           const float* __restrict__ attn_h,
           const float* __restrict__ pool_w,
           const float* __restrict__ pool_b,
           float* __restrict__ out)
{
    extern __shared__ __align__(16) char sm[];
    __shared__ float w5[EDIM][8];
    __shared__ float rm[4], rse[4], rsq[4];

    const int t = threadIdx.x;
    const int b = blockIdx.x;
    const float* xb = x + (size_t)b * (FDIM * EDIM);

    // ================= prologue: split x, build 5 y-tables (bf16 hi/lo) ======
    const int f = t & 63;
    const int h = t >> 6;             // e-half
    const float* src = xb + f * EDIM + h * 16;
    float4 v4[4];
    #pragma unroll
    for (int q = 0; q < 4; q++) v4[q] = reinterpret_cast<const float4*>(src)[q];

    if (t < EDIM) {
        float4 wv = reinterpret_cast<const float4*>(attn_w)[t];
        w5[t][0] = wv.x; w5[t][1] = wv.y; w5[t][2] = wv.z; w5[t][3] = wv.w;
        w5[t][4] = pool_w[t];
    }
    __syncthreads();

    float v[16];
    #pragma unroll
    for (int q = 0; q < 4; q++) {
        v[q * 4 + 0] = v4[q].x; v[q * 4 + 1] = v4[q].y;
        v[q * 4 + 2] = v4[q].z; v[q * 4 + 3] = v4[q].w;
    }

    const int fs = (f >> 1) & 3;      // row swizzle term
    #pragma unroll
    for (int c = 0; c < 2; c++) {     // chunk of 8 e (one uint4)
        uint32_t xh4[4], xl4[4], yh4[5][4], yl4[5][4];
        #pragma unroll
        for (int p = 0; p < 4; p++) {
            int ei = c * 8 + p * 2;
            int e  = h * 16 + ei;
            float a0 = v[ei], a1 = v[ei + 1];
            uint32_t u0 = __float_as_uint(a0), u1 = __float_as_uint(a1);
            xh4[p] = __byte_perm(u0, u1, 0x7632);
            float t0 = a0 - __uint_as_float(u0 & 0xFFFF0000u);
            float t1 = a1 - __uint_as_float(u1 & 0xFFFF0000u);
            xl4[p] = pack_bf16x2(t1, t0);
            float4 wr0 = *reinterpret_cast<const float4*>(&w5[e][0]);
            float4 wr1 = *reinterpret_cast<const float4*>(&w5[e + 1][0]);
            float wa0[5] = { wr0.x, wr0.y, wr0.z, wr0.w, w5[e][4] };
            float wa1[5] = { wr1.x, wr1.y, wr1.z, wr1.w, w5[e + 1][4] };
            #pragma unroll
            for (int a = 0; a < 5; a++) {
                float y0 = a0 * wa0[a], y1 = a1 * wa1[a];
                uint32_t q0 = __float_as_uint(y0), q1 = __float_as_uint(y1);
                yh4[a][p] = __byte_perm(q0, q1, 0x7632);
                float g0 = y0 - __uint_as_float(q0 & 0xFFFF0000u);
                float g1 = y1 - __uint_as_float(q1 & 0xFFFF0000u);
                yl4[a][p] = pack_bf16x2(g1, g0);
            }
        }
        // swizzled 16B-chunk store: chunk index = (h*2+c) ^ fs
        int off = f * ROWBYTES + (((h * 2 + c) ^ fs) << 4);
        *reinterpret_cast<uint4*>(sm + 10 * BUFBYTES + off) = *reinterpret_cast<uint4*>(xh4);
        *reinterpret_cast<uint4*>(sm + 11 * BUFBYTES + off) = *reinterpret_cast<uint4*>(xl4);
        #pragma unroll
        for (int a = 0; a < 5; a++) {
            *reinterpret_cast<uint4*>(sm + (2 * a + 0) * BUFBYTES + off) = *reinterpret_cast<uint4*>(yh4[a]);
            *reinterpret_cast<uint4*>(sm + (2 * a + 1) * BUFBYTES + off) = *reinterpret_cast<uint4*>(yl4[a]);
        }
    }
    __syncthreads();

    // ====== mainloop: A = x (i side), B = y_a (j side), online softmax =======
    const int lane = t & 31;
    const int w    = t >> 5;
    const int lg = lane >> 3, lr = lane & 7;
    const int ls = (lr >> 1) & 3;     // lane swizzle term (tile offsets drop out)

    // explicit dual chunk-select offsets (NO absolute-address XOR — alignment-safe)
    const uint32_t a_row   = (uint32_t)(((lg & 1) * 8 + lr) * ROWBYTES);
    const uint32_t a_csel0 = (uint32_t)((((lg >> 1)    ) ^ ls) << 4);   // e 0..15
    const uint32_t a_csel1 = (uint32_t)((((lg >> 1) | 2) ^ ls) << 4);   // e 16..31
    const uint32_t b_off   = (uint32_t)((lr * ROWBYTES) + ((lg ^ ls) << 4));

    uint32_t smb = (uint32_t)__cvta_generic_to_shared(sm);
    const uint32_t xh0 = smb + 10 * BUFBYTES + a_row + a_csel0;
    const uint32_t xh1 = smb + 10 * BUFBYTES + a_row + a_csel1;
    const uint32_t xl0 = smb + 11 * BUFBYTES + a_row + a_csel0;
    const uint32_t xl1 = smb + 11 * BUFBYTES + a_row + a_csel1;
    const uint32_t b_base = smb + b_off;

    const float ba[4] = { attn_b[0], attn_b[1], attn_b[2], attn_b[3] };
    const float ha[4] = { attn_h[0], attn_h[1], attn_h[2], attn_h[3] };

    const int TI4[4][5] = {{0,0,0,0,0},{0,0,0,1,1},{1,1,1,1,2},{2,2,2,3,3}};
    const int TJ4[4][5] = {{0,1,2,3,4},{5,6,7,2,3},{4,5,6,7,4},{5,6,7,6,7}};

    const int ir0 = (lane >> 2);          // D-frag row base
    const int jc0 = 2 * (lane & 3);       // D-frag col base

    uint32_t ah0[4], ah1[4], al0[4], al1[4];
    int prev_ti = -1;

    float om = -1e30f, ose = 0.f, osq = 0.f;   // online softmax state

    #pragma unroll
    for (int k = 0; k < 5; k++) {
        const int ti = TI4[w][k], tj = TJ4[w][k];

        if (ti != prev_ti) {
            const uint32_t tio = (uint32_t)(ti * 16 * ROWBYTES);
            ldsm4(ah0, xh0 + tio);
            ldsm4(ah1, xh1 + tio);
            ldsm4(al0, xl0 + tio);
            ldsm4(al1, xl1 + tio);
            prev_ti = ti;
        }

        const uint32_t brow = b_base + (uint32_t)(tj * 8 * ROWBYTES);

        float tsc[4] = {0.f, 0.f, 0.f, 0.f};
        float qv[4];
        #pragma unroll
        for (int a = 0; a < 5; a++) {
            uint32_t bh[4], bl[4];
            ldsm4(bh, brow + (uint32_t)((2 * a + 0) * BUFBYTES));
            ldsm4(bl, brow + (uint32_t)((2 * a + 1) * BUFBYTES));

            float d0[4] = {0.f, 0.f, 0.f, 0.f};
            float d1[4] = {0.f, 0.f, 0.f, 0.f};
            mma16816(d0, ah0, bh[0], bh[1]);   // xh·yh k0
            mma16816(d1, ah1, bh[2], bh[3]);   // xh·yh k1
            mma16816(d0, ah0, bl[0], bl[1]);   // xh·yl k0
            mma16816(d1, ah1, bl[2], bl[3]);   // xh·yl k1
            mma16816(d0, al0, bh[0], bh[1]);   // xl·yh k0
            mma16816(d1, al1, bh[2], bh[3]);   // xl·yh k1

            if (a < 4) {
                #pragma unroll
                for (int cc = 0; cc < 4; cc++)
                    tsc[cc] += fmaxf(d0[cc] + d1[cc] + ba[a], 0.f) * ha[a];
            } else {
                #pragma unroll
                for (int cc = 0; cc < 4; cc++) qv[cc] = d0[cc] + d1[cc];
            }
        }

        // mask dead cells (i >= j), online-softmax update
        const int ib = ti * 16 + ir0, jb = tj * 8 + jc0;
        float s[4];
        #pragma unroll
        for (int cc = 0; cc < 4; cc++) {
            int i = ib + ((cc >= 2) ? 8 : 0);
            int j = jb + (cc & 1);
            s[cc] = (i < j) ? tsc[cc] : -1e30f;
        }
        float tmax = fmaxf(fmaxf(s[0], s[1]), fmaxf(s[2], s[3]));
        float mn = fmaxf(om, tmax);
        float scale = __expf(om - mn);
        float e0 = __expf(s[0] - mn), e1 = __expf(s[1] - mn);
        float e2 = __expf(s[2] - mn), e3 = __expf(s[3] - mn);
        ose = ose * scale + (e0 + e1) + (e2 + e3);
        osq = osq * scale + (e0 * qv[0] + e1 * qv[1]) + (e2 * qv[2] + e3 * qv[3]);
        om = mn;
    }

    // ================= merge online states: warp shuffle, then block =========
    #pragma unroll
    for (int o = 16; o; o >>= 1) {
        float m2  = __shfl_xor_sync(0xffffffffu, om,  o);
        float se2 = __shfl_xor_sync(0xffffffffu, ose, o);
        float sq2 = __shfl_xor_sync(0xffffffffu, osq, o);
        float mn = fmaxf(om, m2);
        float s1 = __expf(om - mn), s2 = __expf(m2 - mn);
        ose = ose * s1 + se2 * s2;
        osq = osq * s1 + sq2 * s2;
        om = mn;
    }
    if (lane == 0) { rm[w] = om; rse[w] = ose; rsq[w] = osq; }
    __syncthreads();
    if (t == 0) {
        float M = rm[0], S = rse[0], Q = rsq[0];
        #pragma unroll
        for (int i = 1; i < 4; i++) {
            float mn = fmaxf(M, rm[i]);
            float s1 = __expf(M - mn), s2 = __expf(rm[i] - mn);
            S = S * s1 + rse[i] * s2;
            Q = Q * s1 + rsq[i] * s2;
            M = mn;
        }
        out[b] = Q / S + pool_b[0];
    }
}

extern "C" void kernel_launch(void* const* d_in, const int* in_sizes, int n_in,
                              void* d_out, int out_size)
{
    const float* x      = (const float*)d_in[0];
    const float* attn_w = (const float*)d_in[1];
    const float* attn_b = (const float*)d_in[2];
    const float* attn_h = (const float*)d_in[3];
    const float* pool_w = (const float*)d_in[4];
    const float* pool_b = (const float*)d_in[5];
    float* out = (float*)d_out;

    cudaFuncSetAttribute(afm_kernel, cudaFuncAttributeMaxDynamicSharedMemorySize, SMEM_BYTES);

    int B = in_sizes[0] / (FDIM * EDIM);
    afm_kernel<<<B, THREADS, SMEM_BYTES>>>(x, attn_w, attn_b, attn_h, pool_w, pool_b, out);
}

// round 9
// speedup vs baseline: 1.0800x; 1.0218x over previous
#include <cuda_runtime.h>
#include <cstdint>

#define THREADS   128
#define FDIM      64
#define EDIM      32
#define ROWBYTES  64                  // 32 bf16, XOR-swizzled 16B chunks (no pad)
#define BUFBYTES  (FDIM * ROWBYTES)   // 4096 B per [64][32] bf16 buffer
#define NBUF      12                  // 0..9 = head*2+{h,l} of y; 10 = xh; 11 = xl
#define SMEM_BYTES (NBUF * BUFBYTES)  // 49152

static __device__ __forceinline__ uint32_t pack_bf16x2(float hi, float lo) {
    uint32_t r;
    asm("cvt.rn.bf16x2.f32 %0, %1, %2;" : "=r"(r) : "f"(hi), "f"(lo));
    return r;
}
static __device__ __forceinline__ void ldsm4(uint32_t* r, uint32_t addr) {
    asm volatile("ldmatrix.sync.aligned.m8n8.x4.shared.b16 {%0,%1,%2,%3}, [%4];"
                 : "=r"(r[0]), "=r"(r[1]), "=r"(r[2]), "=r"(r[3]) : "r"(addr));
}
static __device__ __forceinline__ void mma16816(float* d, const uint32_t* a,
                                                uint32_t b0, uint32_t b1) {
    asm volatile("mma.sync.aligned.m16n8k16.row.col.f32.bf16.bf16.f32 "
                 "{%0,%1,%2,%3}, {%4,%5,%6,%7}, {%8,%9}, {%0,%1,%2,%3};"
                 : "+f"(d[0]), "+f"(d[1]), "+f"(d[2]), "+f"(d[3])
                 : "r"(a[0]), "r"(a[1]), "r"(a[2]), "r"(a[3]), "r"(b0), "r"(b1));
}

__global__ void __launch_bounds__(THREADS, 4)
afm_kernel(const float* __restrict__ x,
           const float* __restrict__ attn_w,
           const float* __restrict__ attn_b,
           const float* __restrict__ attn_h,
           const float* __restrict__ pool_w,
           const float* __restrict__ pool_b,
           float* __restrict__ out)
{
    extern __shared__ __align__(16) char sm[];
    __shared__ float w5[EDIM][8];
    __shared__ float rm[4], rse[4], rsq[4];

    const int t = threadIdx.x;
    const int b = blockIdx.x;
    const float* xb = x + (size_t)b * (FDIM * EDIM);

    // ================= prologue: split x, build 5 y-tables (bf16 hi/lo) ======
    const int f = t & 63;
    const int h = t >> 6;             // e-half
    const float* src = xb + f * EDIM + h * 16;
    float4 v4[4];
    #pragma unroll
    for (int q = 0; q < 4; q++) v4[q] = reinterpret_cast<const float4*>(src)[q];

    if (t < EDIM) {
        float4 wv = reinterpret_cast<const float4*>(attn_w)[t];
        w5[t][0] = wv.x; w5[t][1] = wv.y; w5[t][2] = wv.z; w5[t][3] = wv.w;
        w5[t][4] = pool_w[t];
    }
    __syncthreads();

    float v[16];
    #pragma unroll
    for (int q = 0; q < 4; q++) {
        v[q * 4 + 0] = v4[q].x; v[q * 4 + 1] = v4[q].y;
        v[q * 4 + 2] = v4[q].z; v[q * 4 + 3] = v4[q].w;
    }

    const int fs = (f >> 1) & 3;      // row swizzle term
    #pragma unroll
    for (int c = 0; c < 2; c++) {     // chunk of 8 e (one uint4)
        uint32_t xh4[4], xl4[4], yh4[5][4], yl4[5][4];
        #pragma unroll
        for (int p = 0; p < 4; p++) {
            int ei = c * 8 + p * 2;
            int e  = h * 16 + ei;
            float a0 = v[ei], a1 = v[ei + 1];
            uint32_t u0 = __float_as_uint(a0), u1 = __float_as_uint(a1);
            xh4[p] = __byte_perm(u0, u1, 0x7632);
            float t0 = a0 - __uint_as_float(u0 & 0xFFFF0000u);
            float t1 = a1 - __uint_as_float(u1 & 0xFFFF0000u);
            xl4[p] = pack_bf16x2(t1, t0);
            float4 wr0 = *reinterpret_cast<const float4*>(&w5[e][0]);
            float4 wr1 = *reinterpret_cast<const float4*>(&w5[e + 1][0]);
            float wa0[5] = { wr0.x, wr0.y, wr0.z, wr0.w, w5[e][4] };
            float wa1[5] = { wr1.x, wr1.y, wr1.z, wr1.w, w5[e + 1][4] };
            #pragma unroll
            for (int a = 0; a < 5; a++) {
                float y0 = a0 * wa0[a], y1 = a1 * wa1[a];
                uint32_t q0 = __float_as_uint(y0), q1 = __float_as_uint(y1);
                yh4[a][p] = __byte_perm(q0, q1, 0x7632);
                float g0 = y0 - __uint_as_float(q0 & 0xFFFF0000u);
                float g1 = y1 - __uint_as_float(q1 & 0xFFFF0000u);
                yl4[a][p] = pack_bf16x2(g1, g0);
            }
        }
        int off = f * ROWBYTES + (((h * 2 + c) ^ fs) << 4);
        *reinterpret_cast<uint4*>(sm + 10 * BUFBYTES + off) = *reinterpret_cast<uint4*>(xh4);
        *reinterpret_cast<uint4*>(sm + 11 * BUFBYTES + off) = *reinterpret_cast<uint4*>(xl4);
        #pragma unroll
        for (int a = 0; a < 5; a++) {
            *reinterpret_cast<uint4*>(sm + (2 * a + 0) * BUFBYTES + off) = *reinterpret_cast<uint4*>(yh4[a]);
            *reinterpret_cast<uint4*>(sm + (2 * a + 1) * BUFBYTES + off) = *reinterpret_cast<uint4*>(yl4[a]);
        }
    }
    __syncthreads();

    // ====== mainloop: A = x (i side), B = y_a (j side), online softmax =======
    const int lane = t & 31;
    const int w    = t >> 5;
    const int lg = lane >> 3, lr = lane & 7;
    const int ls = (lr >> 1) & 3;

    const uint32_t a_row   = (uint32_t)(((lg & 1) * 8 + lr) * ROWBYTES);
    const uint32_t a_csel0 = (uint32_t)((((lg >> 1)    ) ^ ls) << 4);   // e 0..15
    const uint32_t a_csel1 = (uint32_t)((((lg >> 1) | 2) ^ ls) << 4);   // e 16..31
    const uint32_t b_off   = (uint32_t)((lr * ROWBYTES) + ((lg ^ ls) << 4));

    uint32_t smb = (uint32_t)__cvta_generic_to_shared(sm);
    const uint32_t xh0 = smb + 10 * BUFBYTES + a_row + a_csel0;
    const uint32_t xh1 = smb + 10 * BUFBYTES + a_row + a_csel1;
    const uint32_t xl0 = smb + 11 * BUFBYTES + a_row + a_csel0;
    const uint32_t xl1 = smb + 11 * BUFBYTES + a_row + a_csel1;
    const uint32_t b_base = smb + b_off;

    const float ba[4] = { attn_b[0], attn_b[1], attn_b[2], attn_b[3] };
    const float ha[4] = { attn_h[0], attn_h[1], attn_h[2], attn_h[3] };

    const int TI4[4][5] = {{0,0,0,0,0},{0,0,0,1,1},{1,1,1,1,2},{2,2,2,3,3}};
    const int TJ4[4][5] = {{0,1,2,3,4},{5,6,7,2,3},{4,5,6,7,4},{5,6,7,6,7}};
    // tiles touching the diagonal (tj==2ti or 2ti+1) -> need cell masking
    const int DIAGMASK[4] = { 0x03, 0x18, 0x10, 0x19 };

    const int ir0 = (lane >> 2);
    const int jc0 = 2 * (lane & 3);

    uint32_t ah0[4], ah1[4], al0[4], al1[4];
    int prev_ti = -1;

    float om = -1e30f, ose = 0.f, osq = 0.f;
    const int dmask = DIAGMASK[w];

    #pragma unroll
    for (int k = 0; k < 5; k++) {
        const int ti = TI4[w][k], tj = TJ4[w][k];

        if (ti != prev_ti) {
            const uint32_t tio = (uint32_t)(ti * 16 * ROWBYTES);
            ldsm4(ah0, xh0 + tio);
            ldsm4(ah1, xh1 + tio);
            ldsm4(al0, xl0 + tio);
            ldsm4(al1, xl1 + tio);
            prev_ti = ti;
        }

        const uint32_t brow = b_base + (uint32_t)(tj * 8 * ROWBYTES);

        float tsc[4];
        float qv[4];
        #pragma unroll
        for (int a = 0; a < 5; a++) {
            uint32_t bh[4], bl[4];
            ldsm4(bh, brow + (uint32_t)((2 * a + 0) * BUFBYTES));
            ldsm4(bl, brow + (uint32_t)((2 * a + 1) * BUFBYTES));

            // single accumulator, bias preloaded (saves movs + adds)
            float d[4];
            const float init = (a < 4) ? ba[a] : 0.f;
            d[0] = init; d[1] = init; d[2] = init; d[3] = init;

            mma16816(d, ah0, bh[0], bh[1]);   // xh·yh k0
            mma16816(d, ah1, bh[2], bh[3]);   // xh·yh k1
            mma16816(d, ah0, bl[0], bl[1]);   // xh·yl k0
            mma16816(d, ah1, bl[2], bl[3]);   // xh·yl k1
            mma16816(d, al0, bh[0], bh[1]);   // xl·yh k0
            mma16816(d, al1, bh[2], bh[3]);   // xl·yh k1

            if (a == 0) {
                #pragma unroll
                for (int cc = 0; cc < 4; cc++)
                    tsc[cc] = fmaxf(d[cc], 0.f) * ha[0];
            } else if (a < 4) {
                #pragma unroll
                for (int cc = 0; cc < 4; cc++)
                    tsc[cc] += fmaxf(d[cc], 0.f) * ha[a];
            } else {
                #pragma unroll
                for (int cc = 0; cc < 4; cc++) qv[cc] = d[cc];
            }
        }

        // mask only diagonal-touching tiles (warp-uniform branch)
        float s[4];
        if ((dmask >> k) & 1) {
            const int ib = ti * 16 + ir0, jb = tj * 8 + jc0;
            #pragma unroll
            for (int cc = 0; cc < 4; cc++) {
                int i = ib + ((cc >= 2) ? 8 : 0);
                int j = jb + (cc & 1);
                s[cc] = (i < j) ? tsc[cc] : -1e30f;
            }
        } else {
            #pragma unroll
            for (int cc = 0; cc < 4; cc++) s[cc] = tsc[cc];
        }

        float tmax = fmaxf(fmaxf(s[0], s[1]), fmaxf(s[2], s[3]));
        float mn = fmaxf(om, tmax);
        float scale = __expf(om - mn);
        float e0 = __expf(s[0] - mn), e1 = __expf(s[1] - mn);
        float e2 = __expf(s[2] - mn), e3 = __expf(s[3] - mn);
        ose = ose * scale + (e0 + e1) + (e2 + e3);
        osq = osq * scale + (e0 * qv[0] + e1 * qv[1]) + (e2 * qv[2] + e3 * qv[3]);
        om = mn;
    }

    // ================= merge online states: warp shuffle, then block =========
    #pragma unroll
    for (int o = 16; o; o >>= 1) {
        float m2  = __shfl_xor_sync(0xffffffffu, om,  o);
        float se2 = __shfl_xor_sync(0xffffffffu, ose, o);
        float sq2 = __shfl_xor_sync(0xffffffffu, osq, o);
        float mn = fmaxf(om, m2);
        float s1 = __expf(om - mn), s2 = __expf(m2 - mn);
        ose = ose * s1 + se2 * s2;
        osq = osq * s1 + sq2 * s2;
        om = mn;
    }
    if (lane == 0) { rm[w] = om; rse[w] = ose; rsq[w] = osq; }
    __syncthreads();
    if (t == 0) {
        float M = rm[0], S = rse[0], Q = rsq[0];
        #pragma unroll
        for (int i = 1; i < 4; i++) {
            float mn = fmaxf(M, rm[i]);
            float s1 = __expf(M - mn), s2 = __expf(rm[i] - mn);
            S = S * s1 + rse[i] * s2;
            Q = Q * s1 + rsq[i] * s2;
            M = mn;
        }
        out[b] = Q / S + pool_b[0];
    }
}

extern "C" void kernel_launch(void* const* d_in, const int* in_sizes, int n_in,
                              void* d_out, int out_size)
{
    const float* x      = (const float*)d_in[0];
    const float* attn_w = (const float*)d_in[1];
    const float* attn_b = (const float*)d_in[2];
    const float* attn_h = (const float*)d_in[3];
    const float* pool_w = (const float*)d_in[4];
    const float* pool_b = (const float*)d_in[5];
    float* out = (float*)d_out;

    cudaFuncSetAttribute(afm_kernel, cudaFuncAttributeMaxDynamicSharedMemorySize, SMEM_BYTES);

    int B = in_sizes[0] / (FDIM * EDIM);
    afm_kernel<<<B, THREADS, SMEM_BYTES>>>(x, attn_w, attn_b, attn_h, pool_w, pool_b, out);
}

// round 10
// speedup vs baseline: 1.1393x; 1.0548x over previous
#include <cuda_runtime.h>
#include <cstdint>

#define THREADS   128
#define FDIM      64
#define EDIM      32
#define ROWBYTES  64                  // 32 bf16, XOR-swizzled 16B chunks (no pad)
#define BUFBYTES  (FDIM * ROWBYTES)   // 4096 B per [64][32] bf16 buffer
#define NBUF      12                  // 0..9 = head*2+{h,l} of y; 10 = xh; 11 = xl
#define SMEM_BYTES (NBUF * BUFBYTES)  // 49152

static __device__ __forceinline__ uint32_t pack_bf16x2(float hi, float lo) {
    uint32_t r;
    asm("cvt.rn.bf16x2.f32 %0, %1, %2;" : "=r"(r) : "f"(hi), "f"(lo));
    return r;
}
static __device__ __forceinline__ void ldsm4(uint32_t* r, uint32_t addr) {
    asm volatile("ldmatrix.sync.aligned.m8n8.x4.shared.b16 {%0,%1,%2,%3}, [%4];"
                 : "=r"(r[0]), "=r"(r[1]), "=r"(r[2]), "=r"(r[3]) : "r"(addr));
}
static __device__ __forceinline__ void mma16816(float* d, const uint32_t* a,
                                                uint32_t b0, uint32_t b1) {
    asm volatile("mma.sync.aligned.m16n8k16.row.col.f32.bf16.bf16.f32 "
                 "{%0,%1,%2,%3}, {%4,%5,%6,%7}, {%8,%9}, {%0,%1,%2,%3};"
                 : "+f"(d[0]), "+f"(d[1]), "+f"(d[2]), "+f"(d[3])
                 : "r"(a[0]), "r"(a[1]), "r"(a[2]), "r"(a[3]), "r"(b0), "r"(b1));
}
// first MMA of a chain: explicit zero C operand (ptxas -> RZ, no init movs)
static __device__ __forceinline__ void mma16816_zc(float* d, const uint32_t* a,
                                                   uint32_t b0, uint32_t b1) {
    asm volatile("mma.sync.aligned.m16n8k16.row.col.f32.bf16.bf16.f32 "
                 "{%0,%1,%2,%3}, {%4,%5,%6,%7}, {%8,%9}, {%10,%10,%10,%10};"
                 : "=f"(d[0]), "=f"(d[1]), "=f"(d[2]), "=f"(d[3])
                 : "r"(a[0]), "r"(a[1]), "r"(a[2]), "r"(a[3]), "r"(b0), "r"(b1),
                   "f"(0.0f));
}

__global__ void __launch_bounds__(THREADS, 4)
afm_kernel(const float* __restrict__ x,
           const float* __restrict__ attn_w,
           const float* __restrict__ attn_b,
           const float* __restrict__ attn_h,
           const float* __restrict__ pool_w,
           const float* __restrict__ pool_b,
           float* __restrict__ out)
{
    extern __shared__ __align__(16) char sm[];
    __shared__ float w5[EDIM][8];
    __shared__ float rm[4], rse[4], rsq[4];

    const int t = threadIdx.x;
    const int b = blockIdx.x;
    const float* xb = x + (size_t)b * (FDIM * EDIM);

    // ================= prologue: split x, build 5 y-tables (bf16 hi/lo) ======
    const int f = t & 63;
    const int h = t >> 6;             // e-half
    const float* src = xb + f * EDIM + h * 16;
    float4 v4[4];
    #pragma unroll
    for (int q = 0; q < 4; q++) v4[q] = reinterpret_cast<const float4*>(src)[q];

    if (t < EDIM) {
        float4 wv = reinterpret_cast<const float4*>(attn_w)[t];
        w5[t][0] = wv.x; w5[t][1] = wv.y; w5[t][2] = wv.z; w5[t][3] = wv.w;
        w5[t][4] = pool_w[t];
    }
    __syncthreads();

    float v[16];
    #pragma unroll
    for (int q = 0; q < 4; q++) {
        v[q * 4 + 0] = v4[q].x; v[q * 4 + 1] = v4[q].y;
        v[q * 4 + 2] = v4[q].z; v[q * 4 + 3] = v4[q].w;
    }

    const int fs = (f >> 1) & 3;      // row swizzle term
    #pragma unroll
    for (int c = 0; c < 2; c++) {     // chunk of 8 e (one uint4)
        uint32_t xh4[4], xl4[4], yh4[5][4], yl4[5][4];
        #pragma unroll
        for (int p = 0; p < 4; p++) {
            int ei = c * 8 + p * 2;
            int e  = h * 16 + ei;
            float a0 = v[ei], a1 = v[ei + 1];
            uint32_t u0 = __float_as_uint(a0), u1 = __float_as_uint(a1);
            xh4[p] = __byte_perm(u0, u1, 0x7632);
            float t0 = a0 - __uint_as_float(u0 & 0xFFFF0000u);
            float t1 = a1 - __uint_as_float(u1 & 0xFFFF0000u);
            xl4[p] = pack_bf16x2(t1, t0);
            float4 wr0 = *reinterpret_cast<const float4*>(&w5[e][0]);
            float4 wr1 = *reinterpret_cast<const float4*>(&w5[e + 1][0]);
            float wa0[5] = { wr0.x, wr0.y, wr0.z, wr0.w, w5[e][4] };
            float wa1[5] = { wr1.x, wr1.y, wr1.z, wr1.w, w5[e + 1][4] };
            #pragma unroll
            for (int a = 0; a < 5; a++) {
                float y0 = a0 * wa0[a], y1 = a1 * wa1[a];
                uint32_t q0 = __float_as_uint(y0), q1 = __float_as_uint(y1);
                yh4[a][p] = __byte_perm(q0, q1, 0x7632);
                float g0 = y0 - __uint_as_float(q0 & 0xFFFF0000u);
                float g1 = y1 - __uint_as_float(q1 & 0xFFFF0000u);
                yl4[a][p] = pack_bf16x2(g1, g0);
            }
        }
        int off = f * ROWBYTES + (((h * 2 + c) ^ fs) << 4);
        *reinterpret_cast<uint4*>(sm + 10 * BUFBYTES + off) = *reinterpret_cast<uint4*>(xh4);
        *reinterpret_cast<uint4*>(sm + 11 * BUFBYTES + off) = *reinterpret_cast<uint4*>(xl4);
        #pragma unroll
        for (int a = 0; a < 5; a++) {
            *reinterpret_cast<uint4*>(sm + (2 * a + 0) * BUFBYTES + off) = *reinterpret_cast<uint4*>(yh4[a]);
            *reinterpret_cast<uint4*>(sm + (2 * a + 1) * BUFBYTES + off) = *reinterpret_cast<uint4*>(yl4[a]);
        }
    }
    __syncthreads();

    // ====== mainloop: A = x (i side), B = y_a (j side), online softmax =======
    const int lane = t & 31;
    const int w    = t >> 5;
    const int lg = lane >> 3, lr = lane & 7;
    const int ls = (lr >> 1) & 3;

    const uint32_t a_row   = (uint32_t)(((lg & 1) * 8 + lr) * ROWBYTES);
    const uint32_t a_csel0 = (uint32_t)((((lg >> 1)    ) ^ ls) << 4);   // e 0..15
    const uint32_t a_csel1 = (uint32_t)((((lg >> 1) | 2) ^ ls) << 4);   // e 16..31
    const uint32_t b_off   = (uint32_t)((lr * ROWBYTES) + ((lg ^ ls) << 4));

    uint32_t smb = (uint32_t)__cvta_generic_to_shared(sm);
    const uint32_t xh0 = smb + 10 * BUFBYTES + a_row + a_csel0;
    const uint32_t xh1 = smb + 10 * BUFBYTES + a_row + a_csel1;
    const uint32_t xl0 = smb + 11 * BUFBYTES + a_row + a_csel0;
    const uint32_t xl1 = smb + 11 * BUFBYTES + a_row + a_csel1;
    const uint32_t b_base = smb + b_off;

    // bias folded into relu threshold: relu(d+b)*h = max(d,-b)*h + b*h;
    // the constant sum(b_a*h_a) cancels under softmax -> dropped entirely.
    const float nb[4] = { -attn_b[0], -attn_b[1], -attn_b[2], -attn_b[3] };
    const float ha[4] = {  attn_h[0],  attn_h[1],  attn_h[2],  attn_h[3] };

    const int TI4[4][5] = {{0,0,0,0,0},{0,0,0,1,1},{1,1,1,1,2},{2,2,2,3,3}};
    const int TJ4[4][5] = {{0,1,2,3,4},{5,6,7,2,3},{4,5,6,7,4},{5,6,7,6,7}};
    const int DIAGMASK[4] = { 0x03, 0x18, 0x10, 0x19 };   // diagonal-touching tiles

    const int ir0 = (lane >> 2);
    const int jc0 = 2 * (lane & 3);

    uint32_t ah0[4], ah1[4], al0[4], al1[4];
    int prev_ti = -1;

    float om = -1e30f, ose = 0.f, osq = 0.f;
    const int dmask = DIAGMASK[w];

    #pragma unroll
    for (int k = 0; k < 5; k++) {
        const int ti = TI4[w][k], tj = TJ4[w][k];

        if (ti != prev_ti) {
            const uint32_t tio = (uint32_t)(ti * 16 * ROWBYTES);
            ldsm4(ah0, xh0 + tio);
            ldsm4(ah1, xh1 + tio);
            ldsm4(al0, xl0 + tio);
            ldsm4(al1, xl1 + tio);
            prev_ti = ti;
        }

        const uint32_t brow = b_base + (uint32_t)(tj * 8 * ROWBYTES);

        float tsc[4];
        float qv[4];
        #pragma unroll
        for (int a = 0; a < 5; a++) {
            uint32_t bh[4], bl[4];
            ldsm4(bh, brow + (uint32_t)((2 * a + 0) * BUFBYTES));
            ldsm4(bl, brow + (uint32_t)((2 * a + 1) * BUFBYTES));

            float d[4];
            mma16816_zc(d, ah0, bh[0], bh[1]);  // xh·yh k0 (zero C -> RZ)
            mma16816(d, ah1, bh[2], bh[3]);     // xh·yh k1
            mma16816(d, ah0, bl[0], bl[1]);     // xh·yl k0
            mma16816(d, ah1, bl[2], bl[3]);     // xh·yl k1
            mma16816(d, al0, bh[0], bh[1]);     // xl·yh k0
            mma16816(d, al1, bh[2], bh[3]);     // xl·yh k1

            if (a == 0) {
                #pragma unroll
                for (int cc = 0; cc < 4; cc++)
                    tsc[cc] = fmaxf(d[cc], nb[0]) * ha[0];
            } else if (a < 4) {
                #pragma unroll
                for (int cc = 0; cc < 4; cc++)
                    tsc[cc] += fmaxf(d[cc], nb[a]) * ha[a];
            } else {
                #pragma unroll
                for (int cc = 0; cc < 4; cc++) qv[cc] = d[cc];
            }
        }

        // mask only diagonal-touching tiles (warp-uniform branch)
        float s[4];
        if ((dmask >> k) & 1) {
            const int ib = ti * 16 + ir0, jb = tj * 8 + jc0;
            #pragma unroll
            for (int cc = 0; cc < 4; cc++) {
                int i = ib + ((cc >= 2) ? 8 : 0);
                int j = jb + (cc & 1);
                s[cc] = (i < j) ? tsc[cc] : -1e30f;
            }
        } else {
            #pragma unroll
            for (int cc = 0; cc < 4; cc++) s[cc] = tsc[cc];
        }

        float tmax = fmaxf(fmaxf(s[0], s[1]), fmaxf(s[2], s[3]));
        float mn = fmaxf(om, tmax);
        float scale = __expf(om - mn);
        float e0 = __expf(s[0] - mn), e1 = __expf(s[1] - mn);
        float e2 = __expf(s[2] - mn), e3 = __expf(s[3] - mn);
        ose = ose * scale + (e0 + e1) + (e2 + e3);
        osq = osq * scale + (e0 * qv[0] + e1 * qv[1]) + (e2 * qv[2] + e3 * qv[3]);
        om = mn;
    }

    // ================= merge online states: warp shuffle, then block =========
    #pragma unroll
    for (int o = 16; o; o >>= 1) {
        float m2  = __shfl_xor_sync(0xffffffffu, om,  o);
        float se2 = __shfl_xor_sync(0xffffffffu, ose, o);
        float sq2 = __shfl_xor_sync(0xffffffffu, osq, o);
        float mn = fmaxf(om, m2);
        float s1 = __expf(om - mn), s2 = __expf(m2 - mn);
        ose = ose * s1 + se2 * s2;
        osq = osq * s1 + sq2 * s2;
        om = mn;
    }
    if (lane == 0) { rm[w] = om; rse[w] = ose; rsq[w] = osq; }
    __syncthreads();
    if (t == 0) {
        float M = rm[0], S = rse[0], Q = rsq[0];
        #pragma unroll
        for (int i = 1; i < 4; i++) {
            float mn = fmaxf(M, rm[i]);
            float s1 = __expf(M - mn), s2 = __expf(rm[i] - mn);
            S = S * s1 + rse[i] * s2;
            Q = Q * s1 + rsq[i] * s2;
            M = mn;
        }
        out[b] = Q / S + pool_b[0];
    }
}

extern "C" void kernel_launch(void* const* d_in, const int* in_sizes, int n_in,
                              void* d_out, int out_size)
{
    const float* x      = (const float*)d_in[0];
    const float* attn_w = (const float*)d_in[1];
    const float* attn_b = (const float*)d_in[2];
    const float* attn_h = (const float*)d_in[3];
    const float* pool_w = (const float*)d_in[4];
    const float* pool_b = (const float*)d_in[5];
    float* out = (float*)d_out;

    cudaFuncSetAttribute(afm_kernel, cudaFuncAttributeMaxDynamicSharedMemorySize, SMEM_BYTES);

    int B = in_sizes[0] / (FDIM * EDIM);
    afm_kernel<<<B, THREADS, SMEM_BYTES>>>(x, attn_w, attn_b, attn_h, pool_w, pool_b, out);
}